// round 13
// baseline (speedup 1.0000x reference)
#include <cuda_runtime.h>

// Problem constants (fixed by the reference)
#define B_     4
#define N_     4096
#define E_     128
#define CACHE_ 32
#define NK_    4
#define CE_    32      // channels per unit (E / NK)
#define M_     128     // N / CACHE
#define BNE_   (B_*N_*E_)
#define KP_    16      // packed channel pairs per unit (all 32 channels)

// Inter-layer scratch (device globals: no allocation in kernel_launch)
__device__ float g_x [BNE_];
__device__ float g_xa[BNE_];

typedef unsigned long long u64;

__device__ __forceinline__ float tanh_fast(float x) {
    float y;
    asm("tanh.approx.f32 %0, %1;" : "=f"(y) : "f"(x));
    return y;
}
__device__ __forceinline__ u64 pk(float lo, float hi) {
    u64 r; asm("mov.b64 %0, {%1, %2};" : "=l"(r) : "f"(lo), "f"(hi)); return r;
}
__device__ __forceinline__ void upk(u64 x, float& lo, float& hi) {
    asm("mov.b64 {%0, %1}, %2;" : "=f"(lo), "=f"(hi) : "l"(x));
}
__device__ __forceinline__ u64 fma2(u64 a, u64 b, u64 c) {
    u64 d; asm("fma.rn.f32x2 %0, %1, %2, %3;" : "=l"(d) : "l"(a), "l"(b), "l"(c)); return d;
}
__device__ __forceinline__ u64 mul2(u64 a, u64 b) {
    u64 d; asm("mul.rn.f32x2 %0, %1, %2;" : "=l"(d) : "l"(a), "l"(b)); return d;
}
__device__ __forceinline__ u64 add2(u64 a, u64 b) {
    u64 d; asm("add.rn.f32x2 %0, %1, %2;" : "=l"(d) : "l"(a), "l"(b)); return d;
}

// TWO fully independent 1-warp units per 64-thread block (uid = 2*blk + w).
// NO cross-warp sync anywhere: each warp owns a whole (b,g,n) unit.
// lane = row-in-group; 32 channels in registers as 16 packed pairs (u2, v2).
// Rescaled: u2=(xi/2)/0.9^j, v2=(xa/2)/0.9^j; v'=v+c_j*F; u'=u+0.1*v';
// T(true) = sc*(u2 + sim*u2_j). FULL running dots in-register per lane:
// AB2=(Ax,Bx), ab2=(Aa,Ba); sim = Ax[lane] + shfl(Bx, j) — one SHFL.
// Row-j state comes from a warp-private smem mirror: lane j+1 publishes its
// updated u2 (8 STS.128) at step end; all lanes read it (8 broadcast
// LDS.128) at the next step top; __syncwarp fences order it.
// Reg budget: __launch_bounds__(64,7) -> 146 regs (natural ~120, slack for
// scheduling — the R7 failure was a hard 128-reg ceiling).
__global__ void __launch_bounds__(64, 7)
ncn_layer(const float* __restrict__ X, const float* __restrict__ XA,
          const float* __restrict__ W,         // 256 floats: Wi[4][32], Wj[4][32]
          float* __restrict__ YX, float* __restrict__ YA,
          int s)                                // group-index stride (0 or 1)
{
    __shared__ float tile[2][CACHE_][CACHE_ + 1];   // per-warp transpose tile
    __shared__ __align__(16) u64 sW[2][2 * KP_];    // per-warp (Wi2,Wj2) pairs
    __shared__ __align__(16) u64 mir[2][KP_];       // per-warp row-j mirror

    const int t    = threadIdx.x;
    const int w    = t >> 5;                    // warp in block (0/1)
    const int lane = t & 31;                    // row-in-group
    const int uid  = blockIdx.x * 2 + w;        // unit id 0..2047
    const int n    = uid & (NK_ - 1);
    const int g    = (uid >> 2) & (M_ - 1);
    const int b    = uid >> 9;

    if (lane < KP_) {
        int c = n * CE_ + 2 * lane;
        sW[w][2 * lane]     = pk(W[c],      W[c + 1]);      // (Wi_c0, Wi_c1)
        sW[w][2 * lane + 1] = pk(W[E_ + c], W[E_ + c + 1]); // (Wj_c0, Wj_c1)
    }
    __syncwarp();

    const long long bBase    = (long long)b * N_ * E_;
    const long long chanBase = (long long)n * CE_ + lane;
    const ulonglong2* sWv = reinterpret_cast<const ulonglong2*>(sW[w]);

    u64 u2[KP_], v2[KP_];

    // ---- gather xi tile (coalesced per row, warp-private transpose) ----
    #pragma unroll
    for (int r = 0; r < CACHE_; ++r) {
        int row = ((g + r * s) & (M_ - 1)) * CACHE_ + r;
        tile[w][r][lane] = X[bBase + (long long)row * E_ + chanBase];
    }
    __syncwarp();
    #pragma unroll
    for (int k = 0; k < KP_; ++k)
        u2[k] = pk(0.5f * tile[w][lane][2 * k], 0.5f * tile[w][lane][2 * k + 1]);
    __syncwarp();

    // ---- gather xa tile ----
    #pragma unroll
    for (int r = 0; r < CACHE_; ++r) {
        int row = ((g + r * s) & (M_ - 1)) * CACHE_ + r;
        tile[w][r][lane] = XA[bBase + (long long)row * E_ + chanBase];
    }
    __syncwarp();
    #pragma unroll
    for (int k = 0; k < KP_; ++k)
        v2[k] = pk(0.5f * tile[w][lane][2 * k], 0.5f * tile[w][lane][2 * k + 1]);

    const u64 K09 = pk(0.9f, 0.9f);
    const u64 K01 = pk(0.1f, 0.1f);
    const u64 Z   = pk(0.f, 0.f);

    // ---- initial full running dots (true scale = 2 * half-scale dot) ----
    u64 AB2, ab2;   // (Ax,Bx), (Aa,Ba)
    {
        u64 ax = Z, bx = Z, aa = Z, ba = Z;
        #pragma unroll
        for (int k = 0; k < KP_; ++k) {
            ulonglong2 ww = sWv[k];             // (Wi2, Wj2)
            ax = fma2(u2[k], ww.x, ax);
            bx = fma2(u2[k], ww.y, bx);
            aa = fma2(v2[k], ww.x, aa);
            ba = fma2(v2[k], ww.y, ba);
        }
        float l, h, Ax, Bx, Aa, Ba;
        upk(ax, l, h); Ax = 2.f * (l + h);
        upk(bx, l, h); Bx = 2.f * (l + h);
        upk(aa, l, h); Aa = 2.f * (l + h);
        upk(ba, l, h); Ba = 2.f * (l + h);
        AB2 = pk(Ax, Bx);
        ab2 = pk(Aa, Ba);
    }

    // mirror row 0's initial state
    if (lane == 0) {
        #pragma unroll
        for (int k2 = 0; k2 < KP_ / 2; ++k2) {
            ulonglong2 tv; tv.x = u2[2 * k2]; tv.y = u2[2 * k2 + 1];
            *reinterpret_cast<ulonglong2*>(&mir[w][2 * k2]) = tv;
        }
    }
    __syncwarp();

    float sc = 1.0f;                  // 0.9^j
    float cj = 0.05f / 0.9f;          // 0.05 / 0.9^(j+1)

    // ---- 32-step recurrence (warp-private, no cross-warp sync) ----
    #pragma unroll 1
    for (int j = 0; j < CACHE_; ++j) {
        // row-j pre-update state (uniform broadcast LDS.128)
        ulonglong2 ujv[KP_ / 2];
        #pragma unroll
        for (int k2 = 0; k2 < KP_ / 2; ++k2)
            ujv[k2] = *reinterpret_cast<const ulonglong2*>(&mir[w][2 * k2]);

        float Ax, Bx; upk(AB2, Ax, Bx);
        float sim = Ax + __shfl_sync(0xffffffffu, Bx, j);

        u64 sim2 = pk(sim, sim);
        u64 s2   = pk(sc, sc);
        u64 c2   = pk(cj, cj);
        u64 SA = Z, SB = Z, DA = Z, DB = Z;     // pair-split dot partials
        #pragma unroll
        for (int k = 0; k < KP_; ++k) {
            u64 uj = (k & 1) ? ujv[k >> 1].y : ujv[k >> 1].x;
            u64 T  = mul2(s2, fma2(sim2, uj, u2[k]));       // true-scale T
            float t0, t1; upk(T, t0, t1);
            u64 F = pk(tanh_fast(t0), tanh_fast(t1));
            ulonglong2 ww = sWv[k];                          // broadcast LDS.128
            if (k & 1) { SB = fma2(F, ww.x, SB); DB = fma2(F, ww.y, DB); }
            else       { SA = fma2(F, ww.x, SA); DA = fma2(F, ww.y, DA); }
            v2[k] = fma2(c2,  F,     v2[k]);                // ~xa update
            u2[k] = fma2(K01, v2[k], u2[k]);                // ~xi update
        }
        float l, h, SF, DF;
        { u64 q = add2(SA, SB); upk(q, l, h); SF = l + h; }
        { u64 q = add2(DA, DB); upk(q, l, h); DF = l + h; }
        u64 S2 = pk(SF, DF);

        ab2 = fma2(ab2, K09, mul2(S2, K01));                // (Aa,Ba)'
        AB2 = fma2(AB2, K09, mul2(ab2, K01));               // (Ax,Bx)'

        // next source row (lane j+1) publishes its updated state
        __syncwarp();                                       // reads done
        if (lane == j + 1) {
            #pragma unroll
            for (int k2 = 0; k2 < KP_ / 2; ++k2) {
                ulonglong2 tv; tv.x = u2[2 * k2]; tv.y = u2[2 * k2 + 1];
                *reinterpret_cast<ulonglong2*>(&mir[w][2 * k2]) = tv;
            }
        }
        __syncwarp();                                       // write visible

        sc *= 0.9f;
        cj *= (1.0f / 0.9f);
    }

    const float fscale = 2.0f * sc;   // undo half-scale and 0.9^32 rescale

    // ---- scatter yi ----
    __syncwarp();
    #pragma unroll
    for (int k = 0; k < KP_; ++k) {
        float l, h; upk(u2[k], l, h);
        tile[w][lane][2 * k]     = fscale * l;
        tile[w][lane][2 * k + 1] = fscale * h;
    }
    __syncwarp();
    #pragma unroll
    for (int r = 0; r < CACHE_; ++r) {
        int row = ((g + r * s) & (M_ - 1)) * CACHE_ + r;
        YX[bBase + (long long)row * E_ + chanBase] = tile[w][r][lane];
    }
    __syncwarp();

    // ---- scatter ya ----
    #pragma unroll
    for (int k = 0; k < KP_; ++k) {
        float l, h; upk(v2[k], l, h);
        tile[w][lane][2 * k]     = fscale * l;
        tile[w][lane][2 * k + 1] = fscale * h;
    }
    __syncwarp();
    #pragma unroll
    for (int r = 0; r < CACHE_; ++r) {
        int row = ((g + r * s) & (M_ - 1)) * CACHE_ + r;
        YA[bBase + (long long)row * E_ + chanBase] = tile[w][r][lane];
    }
}

extern "C" void kernel_launch(void* const* d_in, const int* in_sizes, int n_in,
                              void* d_out, int out_size) {
    const float* x  = (const float*)d_in[0];
    const float* xa = (const float*)d_in[1];
    const float* W  = (const float*)d_in[2];
    float* out = (float*)d_out;

    float *gx = nullptr, *gxa = nullptr;
    cudaGetSymbolAddress((void**)&gx,  g_x);
    cudaGetSymbolAddress((void**)&gxa, g_xa);

    dim3 grid(B_ * M_ * NK_ / 2);   // 1024 blocks, 2 independent units each
    dim3 block(64);

    // Layer 0: stage shift s = 0 (contiguous groups)
    ncn_layer<<<grid, block>>>(x, xa, W, gx, gxa, 0);
    // Layer 1: stage shift s = 1 (block = (g + o) % m), writes final output
    ncn_layer<<<grid, block>>>(gx, gxa, W + 2 * E_, out, out + BNE_, 1);
}